// round 1
// baseline (speedup 1.0000x reference)
#include <cuda_runtime.h>
#include <cuda_bf16.h>

// ---------------------------------------------------------------------------
// GNN layer:
//   out = h@A^T + mean_dst(h[src]*e)@B^T + mean_dst(h[src])@C^T + b_total
// with A = lin@Ws, B = lin@Wn, C = lin@Wu folded on-device,
//      b_total = lin@(Ws_b+Wn_b+Wu_b) + lin_b.
// Pipeline: zero counts -> fuse weights -> histogram(dst) -> scan -> scatter
//           (counting sort by dst) -> warp-per-node aggregation -> fused GEMM.
// ---------------------------------------------------------------------------

#define NODES_CAP 10016
#define EDGES_CAP 640000
#define F 128

static __device__ int   g_counts[NODES_CAP + 1];
static __device__ int   g_offsets[NODES_CAP + 1];
static __device__ int   g_cursor[NODES_CAP];
static __device__ int   g_src_sorted[EDGES_CAP];
static __device__ float g_e_sorted[EDGES_CAP];
static __device__ float g_hp[NODES_CAP * F];   // mean(h[src]*e)
static __device__ float g_hu[NODES_CAP * F];   // mean(h[src])
static __device__ float g_W[F * 3 * F];        // [128][384] row-major: [A|B|C]
static __device__ float g_bias[F];

// ---------------------------------------------------------------------------
__global__ void zero_counts_kernel(int n) {
    int i = blockIdx.x * blockDim.x + threadIdx.x;
    if (i <= n && i <= NODES_CAP) g_counts[i] = 0;
}

// grid (128, 4), 128 threads. seg 0..2: W columns; seg 3: fused bias.
__global__ void fuse_weights_kernel(
    const float* __restrict__ lin_w, const float* __restrict__ lin_b,
    const float* __restrict__ Ws_w, const float* __restrict__ Wn_w,
    const float* __restrict__ Wu_w,
    const float* __restrict__ Ws_b, const float* __restrict__ Wn_b,
    const float* __restrict__ Wu_b)
{
    int n = blockIdx.x;
    int seg = blockIdx.y;
    int i = threadIdx.x;
    __shared__ float linrow[F];
    linrow[i] = lin_w[n * F + i];
    __syncthreads();

    if (seg < 3) {
        const float* Wseg = (seg == 0) ? Ws_w : (seg == 1) ? Wn_w : Wu_w;
        float s = 0.f;
        #pragma unroll 8
        for (int j = 0; j < F; j++)
            s += linrow[j] * Wseg[j * F + i];
        g_W[n * (3 * F) + seg * F + i] = s;
    } else {
        __shared__ float red[F];
        red[i] = linrow[i] * (Ws_b[i] + Wn_b[i] + Wu_b[i]);
        __syncthreads();
        for (int d = 64; d > 0; d >>= 1) {
            if (i < d) red[i] += red[i + d];
            __syncthreads();
        }
        if (i == 0) g_bias[n] = red[0] + lin_b[n];
    }
}

__global__ void hist_kernel(const int* __restrict__ dst, int nE) {
    int i = blockIdx.x * blockDim.x + threadIdx.x;
    if (i < nE) atomicAdd(&g_counts[dst[i]], 1);
}

// Single block, 1024 threads: exclusive scan of counts[0..n-1] -> offsets, cursor.
__global__ void scan_kernel(int n) {
    __shared__ int part[1024];
    int tid = threadIdx.x;
    int per = (n + 1023) >> 10;
    int base = tid * per;
    int local = 0;
    for (int k = 0; k < per; k++) {
        int i = base + k;
        if (i < n) local += g_counts[i];
    }
    part[tid] = local;
    __syncthreads();
    // Hillis-Steele inclusive scan
    for (int d = 1; d < 1024; d <<= 1) {
        int v = (tid >= d) ? part[tid - d] : 0;
        __syncthreads();
        part[tid] += v;
        __syncthreads();
    }
    int run = (tid > 0) ? part[tid - 1] : 0;
    for (int k = 0; k < per; k++) {
        int i = base + k;
        if (i < n) {
            g_offsets[i] = run;
            g_cursor[i]  = run;
            run += g_counts[i];
        }
    }
    if (tid == 1023) g_offsets[n] = part[1023];
}

__global__ void scatter_kernel(const int* __restrict__ src,
                               const int* __restrict__ dst,
                               const float* __restrict__ e, int nE) {
    int i = blockIdx.x * blockDim.x + threadIdx.x;
    if (i < nE) {
        int d = dst[i];
        int pos = atomicAdd(&g_cursor[d], 1);
        if (pos < EDGES_CAP) {
            g_src_sorted[pos] = src[i];
            g_e_sorted[pos]   = e[i];
        }
    }
}

// One warp per node. Lane holds 4 features (float4).
__global__ void agg_kernel(const float* __restrict__ h, int nNodes) {
    int warp = (blockIdx.x * blockDim.x + threadIdx.x) >> 5;
    int lane = threadIdx.x & 31;
    if (warp >= nNodes) return;

    const float4* __restrict__ h4 = (const float4*)h;
    int beg = g_offsets[warp];
    int end = g_offsets[warp + 1];
    int deg = end - beg;

    float4 ap = make_float4(0.f, 0.f, 0.f, 0.f);
    float4 au = ap;
    float4 ap2 = ap, au2 = ap;

    int j = beg;
    for (; j + 4 <= end; j += 4) {
        int s0 = g_src_sorted[j + 0];
        int s1 = g_src_sorted[j + 1];
        int s2 = g_src_sorted[j + 2];
        int s3 = g_src_sorted[j + 3];
        float e0 = g_e_sorted[j + 0];
        float e1 = g_e_sorted[j + 1];
        float e2 = g_e_sorted[j + 2];
        float e3 = g_e_sorted[j + 3];
        float4 v0 = h4[s0 * 32 + lane];
        float4 v1 = h4[s1 * 32 + lane];
        float4 v2 = h4[s2 * 32 + lane];
        float4 v3 = h4[s3 * 32 + lane];
        ap.x += v0.x * e0; ap.y += v0.y * e0; ap.z += v0.z * e0; ap.w += v0.w * e0;
        au.x += v0.x;      au.y += v0.y;      au.z += v0.z;      au.w += v0.w;
        ap2.x += v1.x * e1; ap2.y += v1.y * e1; ap2.z += v1.z * e1; ap2.w += v1.w * e1;
        au2.x += v1.x;      au2.y += v1.y;      au2.z += v1.z;      au2.w += v1.w;
        ap.x += v2.x * e2; ap.y += v2.y * e2; ap.z += v2.z * e2; ap.w += v2.w * e2;
        au.x += v2.x;      au.y += v2.y;      au.z += v2.z;      au.w += v2.w;
        ap2.x += v3.x * e3; ap2.y += v3.y * e3; ap2.z += v3.z * e3; ap2.w += v3.w * e3;
        au2.x += v3.x;      au2.y += v3.y;      au2.z += v3.z;      au2.w += v3.w;
    }
    for (; j < end; j++) {
        int s = g_src_sorted[j];
        float ev = g_e_sorted[j];
        float4 v = h4[s * 32 + lane];
        ap.x += v.x * ev; ap.y += v.y * ev; ap.z += v.z * ev; ap.w += v.w * ev;
        au.x += v.x;      au.y += v.y;      au.z += v.z;      au.w += v.w;
    }
    ap.x += ap2.x; ap.y += ap2.y; ap.z += ap2.z; ap.w += ap2.w;
    au.x += au2.x; au.y += au2.y; au.z += au2.z; au.w += au2.w;

    float inv = 1.f / (float)max(deg, 1);
    float4 op = make_float4(ap.x * inv, ap.y * inv, ap.z * inv, ap.w * inv);
    float4 ou = make_float4(au.x * inv, au.y * inv, au.z * inv, au.w * inv);
    ((float4*)g_hp)[warp * 32 + lane] = op;
    ((float4*)g_hu)[warp * 32 + lane] = ou;
}

// ---------------------------------------------------------------------------
// Fused GEMM: out[M,128] = [h | hp | hu] (M x 384) @ g_W^T (128 x 384) + bias
// Tile: BM=64, BN=128, BK=16; 256 threads; 4x8 micro-tile per thread.
// ---------------------------------------------------------------------------
#define BM 64
#define BN 128
#define BK 16

__global__ __launch_bounds__(256) void gemm_kernel(
    const float* __restrict__ h, float* __restrict__ out, int M)
{
    __shared__ float Xs[BK][BM + 4];
    __shared__ float Wsh[BK][BN + 4];

    int tid = threadIdx.x;
    int tx = tid & 15;   // col group (8 cols each)
    int ty = tid >> 4;   // row group (4 rows each)
    int m0 = blockIdx.x * BM;

    float acc[4][8];
    #pragma unroll
    for (int i = 0; i < 4; i++)
        #pragma unroll
        for (int jj = 0; jj < 8; jj++) acc[i][jj] = 0.f;

    for (int kt = 0; kt < 24; kt++) {
        int k0 = kt * BK;
        int seg = k0 >> 7;
        const float* Xp = (seg == 0) ? h : (seg == 1) ? g_hp : g_hu;
        int kl = k0 & 127;

        // X tile: 64 rows x 16 cols; thread -> (row = tid/4, colgroup = tid%4)
        {
            int row = tid >> 2;
            int cg = tid & 3;
            int gr = m0 + row;
            if (gr >= M) gr = M - 1;
            float4 v = *(const float4*)&Xp[gr * F + kl + cg * 4];
            Xs[cg * 4 + 0][row] = v.x;
            Xs[cg * 4 + 1][row] = v.y;
            Xs[cg * 4 + 2][row] = v.z;
            Xs[cg * 4 + 3][row] = v.w;
        }
        // W tile: 128 rows(n) x 16 cols(k)
        #pragma unroll
        for (int r = 0; r < 2; r++) {
            int idx = tid + r * 256;
            int nrow = idx >> 2;
            int cg = idx & 3;
            float4 v = *(const float4*)&g_W[nrow * (3 * F) + k0 + cg * 4];
            Wsh[cg * 4 + 0][nrow] = v.x;
            Wsh[cg * 4 + 1][nrow] = v.y;
            Wsh[cg * 4 + 2][nrow] = v.z;
            Wsh[cg * 4 + 3][nrow] = v.w;
        }
        __syncthreads();

        #pragma unroll
        for (int k = 0; k < BK; k++) {
            float a[4], b[8];
            *(float4*)a       = *(const float4*)&Xs[k][ty * 4];
            *(float4*)b       = *(const float4*)&Wsh[k][tx * 8];
            *(float4*)(b + 4) = *(const float4*)&Wsh[k][tx * 8 + 4];
            #pragma unroll
            for (int i = 0; i < 4; i++)
                #pragma unroll
                for (int jj = 0; jj < 8; jj++)
                    acc[i][jj] += a[i] * b[jj];
        }
        __syncthreads();
    }

    float bv[8];
    *(float4*)bv       = *(const float4*)&g_bias[tx * 8];
    *(float4*)(bv + 4) = *(const float4*)&g_bias[tx * 8 + 4];

    #pragma unroll
    for (int i = 0; i < 4; i++) {
        int gr = m0 + ty * 4 + i;
        if (gr < M) {
            float4 o0 = make_float4(acc[i][0] + bv[0], acc[i][1] + bv[1],
                                    acc[i][2] + bv[2], acc[i][3] + bv[3]);
            float4 o1 = make_float4(acc[i][4] + bv[4], acc[i][5] + bv[5],
                                    acc[i][6] + bv[6], acc[i][7] + bv[7]);
            *(float4*)&out[gr * F + tx * 8]     = o0;
            *(float4*)&out[gr * F + tx * 8 + 4] = o1;
        }
    }
}

// ---------------------------------------------------------------------------
extern "C" void kernel_launch(void* const* d_in, const int* in_sizes, int n_in,
                              void* d_out, int out_size) {
    const float* h     = (const float*)d_in[0];
    const float* e     = (const float*)d_in[1];
    const int*   src   = (const int*)d_in[2];
    const int*   dst   = (const int*)d_in[3];
    const float* Ws_w  = (const float*)d_in[4];
    const float* Ws_b  = (const float*)d_in[5];
    const float* Wn_w  = (const float*)d_in[6];
    const float* Wn_b  = (const float*)d_in[7];
    const float* Wu_w  = (const float*)d_in[8];
    const float* Wu_b  = (const float*)d_in[9];
    const float* lin_w = (const float*)d_in[10];
    const float* lin_b = (const float*)d_in[11];
    float* out = (float*)d_out;

    int M = in_sizes[0] / F;   // nodes
    int E = in_sizes[2];       // edges
    if (M > NODES_CAP) M = NODES_CAP;
    if (E > EDGES_CAP) E = EDGES_CAP;

    zero_counts_kernel<<<(M + 256) / 256, 256>>>(M);
    fuse_weights_kernel<<<dim3(F, 4), F>>>(lin_w, lin_b, Ws_w, Wn_w, Wu_w,
                                           Ws_b, Wn_b, Wu_b);
    hist_kernel<<<(E + 255) / 256, 256>>>(dst, E);
    scan_kernel<<<1, 1024>>>(M);
    scatter_kernel<<<(E + 255) / 256, 256>>>(src, dst, e, E);
    agg_kernel<<<(M + 7) / 8, 256>>>(h, M);
    gemm_kernel<<<(M + BM - 1) / BM, 256>>>(h, out, M);
}

// round 4
// speedup vs baseline: 1.0433x; 1.0433x over previous
#include <cuda_runtime.h>
#include <cuda_bf16.h>

// ---------------------------------------------------------------------------
// GNN layer:
//   out = h@A^T + mean_dst(h[src]*e)@B^T + mean_dst(h[src])@C^T + b_total
// A = lin@Ws, B = lin@Wn, C = lin@Wu folded on-device.
// Pipeline: memset counts -> [fuse_weights | hist] (merged kernel) -> scan
//           (warp-shuffle, vectorized) -> scatter (counting sort by dst,
//           packed int2 payload) -> warp-per-node aggregation -> FFMA2 GEMM.
// ---------------------------------------------------------------------------

#define F 128
#define EDGES_CAP 640000
#define SCAN_N 12288            // 1024 threads * 12 elems, >= n_nodes

static __device__ int   g_counts [SCAN_N + 4];
static __device__ int   g_offsets[SCAN_N + 4];
static __device__ int   g_cursor [SCAN_N + 4];
static __device__ int2  g_edge[EDGES_CAP];     // {src, float_bits(e)} sorted by dst
static __device__ float g_hp[SCAN_N * F];      // mean(h[src]*e)
static __device__ float g_hu[SCAN_N * F];      // mean(h[src])
static __device__ float g_W[F * 3 * F];        // [128][384] row-major [A|B|C]
static __device__ float g_bias[F];

// ---------------------------------------------------------------------------
// Merged: blocks [0,128) fold weights; blocks [128, 128+HB) histogram dst.
// ---------------------------------------------------------------------------
__global__ __launch_bounds__(256) void fuse_hist_kernel(
    const float* __restrict__ lin_w, const float* __restrict__ lin_b,
    const float* __restrict__ Ws_w, const float* __restrict__ Wn_w,
    const float* __restrict__ Wu_w,
    const float* __restrict__ Ws_b, const float* __restrict__ Wn_b,
    const float* __restrict__ Wu_b,
    const int* __restrict__ dst, int nE)
{
    int tid = threadIdx.x;
    if (blockIdx.x < F) {
        int n = blockIdx.x;                 // output row of fused weight
        __shared__ float linrow[F];
        if (tid < F) linrow[tid] = lin_w[n * F + tid];
        __syncthreads();

        for (int cc = tid; cc < 3 * F; cc += 256) {
            int seg = cc >> 7, i = cc & 127;
            const float* Wp = (seg == 0) ? Ws_w : (seg == 1) ? Wn_w : Wu_w;
            float s = 0.f;
            #pragma unroll 8
            for (int j = 0; j < F; j++)
                s += linrow[j] * Wp[j * F + i];
            g_W[n * (3 * F) + cc] = s;
        }
        // bias: warp 0, shuffle reduction (no extra barriers)
        if (tid < 32) {
            float s = 0.f;
            #pragma unroll
            for (int m = 0; m < 4; m++) {
                int j = tid + m * 32;
                s += linrow[j] * (Ws_b[j] + Wn_b[j] + Wu_b[j]);
            }
            #pragma unroll
            for (int d = 16; d > 0; d >>= 1)
                s += __shfl_xor_sync(0xffffffffu, s, d);
            if (tid == 0) g_bias[n] = s + lin_b[n];
        }
    } else {
        int i4 = (blockIdx.x - F) * 256 + tid;   // 4 edges per thread
        int base = i4 * 4;
        if (base + 3 < nE) {
            int4 d = *(const int4*)&dst[base];
            atomicAdd(&g_counts[d.x], 1);
            atomicAdd(&g_counts[d.y], 1);
            atomicAdd(&g_counts[d.z], 1);
            atomicAdd(&g_counts[d.w], 1);
        } else {
            for (int q = 0; q < 4; q++)
                if (base + q < nE) atomicAdd(&g_counts[dst[base + q]], 1);
        }
    }
}

// ---------------------------------------------------------------------------
// Single block, 1024 threads, 12 elems/thread, int4 vectorized, shuffle scan.
// counts beyond n_nodes are zero (memset covers SCAN_N), so offsets[n]=E falls
// out naturally.
// ---------------------------------------------------------------------------
__global__ __launch_bounds__(1024) void scan_kernel() {
    __shared__ int wsum[32];
    int tid = threadIdx.x, lane = tid & 31, wid = tid >> 5;

    const int4* c4 = (const int4*)g_counts;
    int4 a = c4[tid * 3 + 0];
    int4 b = c4[tid * 3 + 1];
    int4 c = c4[tid * 3 + 2];
    int v[12] = {a.x, a.y, a.z, a.w, b.x, b.y, b.z, b.w, c.x, c.y, c.z, c.w};
    int local = 0;
    #pragma unroll
    for (int k = 0; k < 12; k++) local += v[k];

    int inc = local;
    #pragma unroll
    for (int d = 1; d < 32; d <<= 1) {
        int t = __shfl_up_sync(0xffffffffu, inc, d);
        if (lane >= d) inc += t;
    }
    if (lane == 31) wsum[wid] = inc;
    __syncthreads();
    if (wid == 0) {
        int s = wsum[lane];
        #pragma unroll
        for (int d = 1; d < 32; d <<= 1) {
            int t = __shfl_up_sync(0xffffffffu, s, d);
            if (lane >= d) s += t;
        }
        wsum[lane] = s;
    }
    __syncthreads();

    int run = (wid ? wsum[wid - 1] : 0) + (inc - local);   // exclusive prefix
    int o[12];
    #pragma unroll
    for (int k = 0; k < 12; k++) { o[k] = run; run += v[k]; }

    int4* off4 = (int4*)g_offsets;
    int4* cur4 = (int4*)g_cursor;
    int4 o0 = make_int4(o[0], o[1], o[2], o[3]);
    int4 o1 = make_int4(o[4], o[5], o[6], o[7]);
    int4 o2 = make_int4(o[8], o[9], o[10], o[11]);
    off4[tid * 3 + 0] = o0; off4[tid * 3 + 1] = o1; off4[tid * 3 + 2] = o2;
    cur4[tid * 3 + 0] = o0; cur4[tid * 3 + 1] = o1; cur4[tid * 3 + 2] = o2;
}

// ---------------------------------------------------------------------------
__global__ __launch_bounds__(256) void scatter_kernel(
    const int* __restrict__ src, const int* __restrict__ dst,
    const float* __restrict__ e, int nE)
{
    int i4 = blockIdx.x * blockDim.x + threadIdx.x;
    int base = i4 * 4;
    if (base + 3 < nE) {
        int4   s  = *(const int4*)&src[base];
        int4   d  = *(const int4*)&dst[base];
        float4 ev = *(const float4*)&e[base];
        int p0 = atomicAdd(&g_cursor[d.x], 1);
        int p1 = atomicAdd(&g_cursor[d.y], 1);
        int p2 = atomicAdd(&g_cursor[d.z], 1);
        int p3 = atomicAdd(&g_cursor[d.w], 1);
        g_edge[p0] = make_int2(s.x, __float_as_int(ev.x));
        g_edge[p1] = make_int2(s.y, __float_as_int(ev.y));
        g_edge[p2] = make_int2(s.z, __float_as_int(ev.z));
        g_edge[p3] = make_int2(s.w, __float_as_int(ev.w));
    } else {
        for (int q = 0; q < 4; q++) {
            int i = base + q;
            if (i < nE) {
                int pos = atomicAdd(&g_cursor[dst[i]], 1);
                g_edge[pos] = make_int2(src[i], __float_as_int(e[i]));
            }
        }
    }
}

// ---------------------------------------------------------------------------
// One warp per node; lane holds 4 features (float4). Unroll-4 for MLP.
// ---------------------------------------------------------------------------
__global__ __launch_bounds__(256) void agg_kernel(const float* __restrict__ h,
                                                  int nNodes)
{
    int warp = (blockIdx.x * blockDim.x + threadIdx.x) >> 5;
    int lane = threadIdx.x & 31;
    if (warp >= nNodes) return;

    const float4* __restrict__ h4 = (const float4*)h;
    int beg = g_offsets[warp];
    int end = g_offsets[warp + 1];
    int deg = end - beg;

    float4 ap = make_float4(0.f, 0.f, 0.f, 0.f), au = ap;
    float4 ap2 = ap, au2 = ap;

    int j = beg;
    for (; j + 4 <= end; j += 4) {
        int2 p0 = g_edge[j + 0];
        int2 p1 = g_edge[j + 1];
        int2 p2 = g_edge[j + 2];
        int2 p3 = g_edge[j + 3];
        float4 v0 = h4[p0.x * 32 + lane];
        float4 v1 = h4[p1.x * 32 + lane];
        float4 v2 = h4[p2.x * 32 + lane];
        float4 v3 = h4[p3.x * 32 + lane];
        float e0 = __int_as_float(p0.y), e1 = __int_as_float(p1.y);
        float e2 = __int_as_float(p2.y), e3 = __int_as_float(p3.y);
        ap.x += v0.x * e0; ap.y += v0.y * e0; ap.z += v0.z * e0; ap.w += v0.w * e0;
        au.x += v0.x;      au.y += v0.y;      au.z += v0.z;      au.w += v0.w;
        ap2.x += v1.x * e1; ap2.y += v1.y * e1; ap2.z += v1.z * e1; ap2.w += v1.w * e1;
        au2.x += v1.x;      au2.y += v1.y;      au2.z += v1.z;      au2.w += v1.w;
        ap.x += v2.x * e2; ap.y += v2.y * e2; ap.z += v2.z * e2; ap.w += v2.w * e2;
        au.x += v2.x;      au.y += v2.y;      au.z += v2.z;      au.w += v2.w;
        ap2.x += v3.x * e3; ap2.y += v3.y * e3; ap2.z += v3.z * e3; ap2.w += v3.w * e3;
        au2.x += v3.x;      au2.y += v3.y;      au2.z += v3.z;      au2.w += v3.w;
    }
    for (; j < end; j++) {
        int2 p = g_edge[j];
        float4 v = h4[p.x * 32 + lane];
        float ev = __int_as_float(p.y);
        ap.x += v.x * ev; ap.y += v.y * ev; ap.z += v.z * ev; ap.w += v.w * ev;
        au.x += v.x;      au.y += v.y;      au.z += v.z;      au.w += v.w;
    }
    ap.x += ap2.x; ap.y += ap2.y; ap.z += ap2.z; ap.w += ap2.w;
    au.x += au2.x; au.y += au2.y; au.z += au2.z; au.w += au2.w;

    float inv = 1.f / (float)max(deg, 1);
    ((float4*)g_hp)[warp * 32 + lane] =
        make_float4(ap.x * inv, ap.y * inv, ap.z * inv, ap.w * inv);
    ((float4*)g_hu)[warp * 32 + lane] =
        make_float4(au.x * inv, au.y * inv, au.z * inv, au.w * inv);
}

// ---------------------------------------------------------------------------
// Fused GEMM: out[M,128] = [h|hp|hu](Mx384) @ g_W^T(128x384) + bias
// BM=64, BN=128, BK=16, 256 threads. Micro-tile 4 rows x 8 cols per thread,
// rows paired for fma.rn.f32x2 (FFMA2). B stored duplicated {w,w} in smem so
// b-pairs load conflict-free as LDS.64; a-pairs come from one LDS.128.
// ---------------------------------------------------------------------------
#define BM 64
#define BN 128
#define BK 16
#define XS_LD 68          // Xs row stride (floats); 68*4=272 = 16*17 (16B ok)

__global__ __launch_bounds__(256) void gemm_kernel(
    const float* __restrict__ h, float* __restrict__ out, int M)
{
    __shared__ float Xs[BK][XS_LD];          // [k][row]
    __shared__ float Wdup[BK][2 * BN];       // [k][2*n] duplicated {w,w}

    int tid = threadIdx.x;
    int tx = tid & 15;                       // col lane: cols tx + 16*m
    int ty = tid >> 4;                       // row group: rows 4*ty..4*ty+3
    int m0 = blockIdx.x * BM;

    unsigned long long acc[2][8];            // [row-pair][col] packed f32x2
    #pragma unroll
    for (int p = 0; p < 2; p++)
        #pragma unroll
        for (int m = 0; m < 8; m++) acc[p][m] = 0ull;

    for (int kt = 0; kt < 24; kt++) {
        int k0 = kt * BK;
        int seg = k0 >> 7;
        const float* Xp = (seg == 0) ? h : (seg == 1) ? g_hp : g_hu;
        int kl = k0 & 127;

        // X tile: 64 rows x 16 k
        {
            int row = tid >> 2;
            int cg  = tid & 3;
            int gr  = m0 + row;
            if (gr >= M) gr = M - 1;
            float4 v = *(const float4*)&Xp[gr * F + kl + cg * 4];
            Xs[cg * 4 + 0][row] = v.x;
            Xs[cg * 4 + 1][row] = v.y;
            Xs[cg * 4 + 2][row] = v.z;
            Xs[cg * 4 + 3][row] = v.w;
        }
        // W tile: 128 n x 16 k, stored duplicated along n
        {
            int n  = tid >> 1;
            int c8 = (tid & 1) * 8;
            float4 v0 = *(const float4*)&g_W[n * (3 * F) + k0 + c8];
            float4 v1 = *(const float4*)&g_W[n * (3 * F) + k0 + c8 + 4];
            float wv[8] = {v0.x, v0.y, v0.z, v0.w, v1.x, v1.y, v1.z, v1.w};
            #pragma unroll
            for (int q = 0; q < 8; q++) {
                float2* dst2 = (float2*)&Wdup[c8 + q][2 * n];
                *dst2 = make_float2(wv[q], wv[q]);
            }
        }
        __syncthreads();

        #pragma unroll
        for (int k = 0; k < BK; k++) {
            // a: rows 4ty..4ty+3 as two packed pairs (one LDS.128)
            ulonglong2 a2 = *(const ulonglong2*)&Xs[k][ty * 4];
            unsigned long long ap0 = a2.x, ap1 = a2.y;
            #pragma unroll
            for (int m = 0; m < 8; m++) {
                unsigned long long b2 =
                    *(const unsigned long long*)&Wdup[k][2 * (tx + 16 * m)];
                asm("fma.rn.f32x2 %0, %1, %2, %0;" : "+l"(acc[0][m])
                    : "l"(ap0), "l"(b2));
                asm("fma.rn.f32x2 %0, %1, %2, %0;" : "+l"(acc[1][m])
                    : "l"(ap1), "l"(b2));
            }
        }
        __syncthreads();
    }

    // Epilogue: unpack, add bias, store (cols tx+16m)
    #pragma unroll
    for (int p = 0; p < 2; p++) {
        int r0 = m0 + ty * 4 + p * 2;
        #pragma unroll
        for (int m = 0; m < 8; m++) {
            int col = tx + 16 * m;
            unsigned lo = (unsigned)(acc[p][m] & 0xffffffffull);
            unsigned hi = (unsigned)(acc[p][m] >> 32);
            float bv = g_bias[col];
            if (r0 < M)     out[r0 * F + col]       = __uint_as_float(lo) + bv;
            if (r0 + 1 < M) out[(r0 + 1) * F + col] = __uint_as_float(hi) + bv;
        }
    }
}

// ---------------------------------------------------------------------------
extern "C" void kernel_launch(void* const* d_in, const int* in_sizes, int n_in,
                              void* d_out, int out_size) {
    const float* h     = (const float*)d_in[0];
    const float* e     = (const float*)d_in[1];
    const int*   src   = (const int*)d_in[2];
    const int*   dst   = (const int*)d_in[3];
    const float* Ws_w  = (const float*)d_in[4];
    const float* Ws_b  = (const float*)d_in[5];
    const float* Wn_w  = (const float*)d_in[6];
    const float* Wn_b  = (const float*)d_in[7];
    const float* Wu_w  = (const float*)d_in[8];
    const float* Wu_b  = (const float*)d_in[9];
    const float* lin_w = (const float*)d_in[10];
    const float* lin_b = (const float*)d_in[11];
    float* out = (float*)d_out;

    int M = in_sizes[0] / F;
    int E = in_sizes[2];
    if (M > SCAN_N) M = SCAN_N;
    if (E > EDGES_CAP) E = EDGES_CAP;

    void* cnt_ptr = 0;
    cudaGetSymbolAddress(&cnt_ptr, g_counts);
    cudaMemsetAsync(cnt_ptr, 0, SCAN_N * sizeof(int));

    int histBlocks = (E + 1023) / 1024;
    fuse_hist_kernel<<<F + histBlocks, 256>>>(lin_w, lin_b, Ws_w, Wn_w, Wu_w,
                                              Ws_b, Wn_b, Wu_b, dst, E);
    scan_kernel<<<1, 1024>>>();
    scatter_kernel<<<(E + 1023) / 1024, 256>>>(src, dst, e, E);
    agg_kernel<<<(M + 7) / 8, 256>>>(h, M);
    gemm_kernel<<<(M + BM - 1) / BM, 256>>>(h, out, M);
}

// round 7
// speedup vs baseline: 1.2022x; 1.1523x over previous
#include <cuda_runtime.h>
#include <cuda_fp16.h>
#include <cstring>

// ---------------------------------------------------------------------------
// GNN layer:
//   out = h@A^T + mean_dst(h[src]*e)@B^T + mean_dst(h[src])@C^T + b_total
// A = lin@Ws, B = lin@Wn, C = lin@Wu folded on-device.
//
// Graph DAG (captured with a stream fork):
//   legacy: fuse_hist -> scan(self-zeroing) -> scatter -> agg -> gemm_pu
//   s2:     convert_h16 ........ gemm_h (h@A^T + bias)
//   joins:  agg waits convert; gemm_pu waits gemm_h.
// Aggregation gathers fp16 h rows (256B/edge instead of 512B), fp32 accum.
// ---------------------------------------------------------------------------

#define F 128
#define EDGES_CAP 640000
#define SCAN_N 12288            // 1024 threads * 12 elems, >= n_nodes

static __device__ int     g_counts [SCAN_N + 4];   // zero-init; scan re-zeroes
static __device__ int     g_offsets[SCAN_N + 4];
static __device__ int     g_cursor [SCAN_N + 4];
static __device__ int2    g_edge[EDGES_CAP];       // {src, bits(e)} sorted by dst
static __device__ __half  g_h16[SCAN_N * F];       // fp16 copy of h
static __device__ float   g_hp[SCAN_N * F];        // mean(h[src]*e)
static __device__ float   g_hu[SCAN_N * F];        // mean(h[src])
static __device__ float   g_W[F * 3 * F];          // [128][384] row-major [A|B|C]
static __device__ float   g_bias[F];

// bit-cast helpers (compile to MOV)
__device__ __forceinline__ unsigned h2_to_u32(__half2 v) {
    unsigned u; memcpy(&u, &v, 4); return u;
}
__device__ __forceinline__ __half2 u32_to_h2(unsigned u) {
    __half2 v; memcpy(&v, &u, 4); return v;
}

// ---------------------------------------------------------------------------
__global__ __launch_bounds__(256) void convert_h16_kernel(
    const float* __restrict__ h, int nElem8)
{
    int i = blockIdx.x * blockDim.x + threadIdx.x;
    if (i >= nElem8) return;
    float4 a = *(const float4*)&h[i * 8];
    float4 b = *(const float4*)&h[i * 8 + 4];
    uint4 o;
    o.x = h2_to_u32(__floats2half2_rn(a.x, a.y));
    o.y = h2_to_u32(__floats2half2_rn(a.z, a.w));
    o.z = h2_to_u32(__floats2half2_rn(b.x, b.y));
    o.w = h2_to_u32(__floats2half2_rn(b.z, b.w));
    *(uint4*)&g_h16[i * 8] = o;
}

// ---------------------------------------------------------------------------
// Merged: blocks [0,128) fold weights; blocks [128, 128+HB) histogram dst.
// ---------------------------------------------------------------------------
__global__ __launch_bounds__(256) void fuse_hist_kernel(
    const float* __restrict__ lin_w, const float* __restrict__ lin_b,
    const float* __restrict__ Ws_w, const float* __restrict__ Wn_w,
    const float* __restrict__ Wu_w,
    const float* __restrict__ Ws_b, const float* __restrict__ Wn_b,
    const float* __restrict__ Wu_b,
    const int* __restrict__ dst, int nE)
{
    int tid = threadIdx.x;
    if (blockIdx.x < F) {
        int n = blockIdx.x;
        __shared__ float linrow[F];
        if (tid < F) linrow[tid] = lin_w[n * F + tid];
        __syncthreads();

        for (int cc = tid; cc < 3 * F; cc += 256) {
            int seg = cc >> 7, i = cc & 127;
            const float* Wp = (seg == 0) ? Ws_w : (seg == 1) ? Wn_w : Wu_w;
            float s = 0.f;
            #pragma unroll 8
            for (int j = 0; j < F; j++)
                s += linrow[j] * Wp[j * F + i];
            g_W[n * (3 * F) + cc] = s;
        }
        if (tid < 32) {
            float s = 0.f;
            #pragma unroll
            for (int m = 0; m < 4; m++) {
                int j = tid + m * 32;
                s += linrow[j] * (Ws_b[j] + Wn_b[j] + Wu_b[j]);
            }
            #pragma unroll
            for (int d = 16; d > 0; d >>= 1)
                s += __shfl_xor_sync(0xffffffffu, s, d);
            if (tid == 0) g_bias[n] = s + lin_b[n];
        }
    } else {
        int base = ((blockIdx.x - F) * 256 + tid) * 4;
        if (base + 3 < nE) {
            int4 d = *(const int4*)&dst[base];
            atomicAdd(&g_counts[d.x], 1);
            atomicAdd(&g_counts[d.y], 1);
            atomicAdd(&g_counts[d.z], 1);
            atomicAdd(&g_counts[d.w], 1);
        } else {
            for (int q = 0; q < 4; q++)
                if (base + q < nE) atomicAdd(&g_counts[dst[base + q]], 1);
        }
    }
}

// ---------------------------------------------------------------------------
// Single block, 1024 threads, 12 elems/thread, int4, shuffle scan.
// Re-zeroes g_counts after reading so every graph replay sees zeros.
// ---------------------------------------------------------------------------
__global__ __launch_bounds__(1024) void scan_kernel() {
    __shared__ int wsum[32];
    int tid = threadIdx.x, lane = tid & 31, wid = tid >> 5;

    int4* c4 = (int4*)g_counts;
    int4 a = c4[tid * 3 + 0];
    int4 b = c4[tid * 3 + 1];
    int4 c = c4[tid * 3 + 2];
    int v[12] = {a.x, a.y, a.z, a.w, b.x, b.y, b.z, b.w, c.x, c.y, c.z, c.w};
    int local = 0;
    #pragma unroll
    for (int k = 0; k < 12; k++) local += v[k];

    // self-zero for next replay
    int4 z = make_int4(0, 0, 0, 0);
    c4[tid * 3 + 0] = z; c4[tid * 3 + 1] = z; c4[tid * 3 + 2] = z;

    int inc = local;
    #pragma unroll
    for (int d = 1; d < 32; d <<= 1) {
        int t = __shfl_up_sync(0xffffffffu, inc, d);
        if (lane >= d) inc += t;
    }
    if (lane == 31) wsum[wid] = inc;
    __syncthreads();
    if (wid == 0) {
        int s = wsum[lane];
        #pragma unroll
        for (int d = 1; d < 32; d <<= 1) {
            int t = __shfl_up_sync(0xffffffffu, s, d);
            if (lane >= d) s += t;
        }
        wsum[lane] = s;
    }
    __syncthreads();

    int run = (wid ? wsum[wid - 1] : 0) + (inc - local);
    int o[12];
    #pragma unroll
    for (int k = 0; k < 12; k++) { o[k] = run; run += v[k]; }

    int4* off4 = (int4*)g_offsets;
    int4* cur4 = (int4*)g_cursor;
    int4 o0 = make_int4(o[0], o[1], o[2], o[3]);
    int4 o1 = make_int4(o[4], o[5], o[6], o[7]);
    int4 o2 = make_int4(o[8], o[9], o[10], o[11]);
    off4[tid * 3 + 0] = o0; off4[tid * 3 + 1] = o1; off4[tid * 3 + 2] = o2;
    cur4[tid * 3 + 0] = o0; cur4[tid * 3 + 1] = o1; cur4[tid * 3 + 2] = o2;
}

// ---------------------------------------------------------------------------
__global__ __launch_bounds__(256) void scatter_kernel(
    const int* __restrict__ src, const int* __restrict__ dst,
    const float* __restrict__ e, int nE)
{
    int base = (blockIdx.x * blockDim.x + threadIdx.x) * 4;
    if (base + 3 < nE) {
        int4   s  = *(const int4*)&src[base];
        int4   d  = *(const int4*)&dst[base];
        float4 ev = *(const float4*)&e[base];
        int p0 = atomicAdd(&g_cursor[d.x], 1);
        int p1 = atomicAdd(&g_cursor[d.y], 1);
        int p2 = atomicAdd(&g_cursor[d.z], 1);
        int p3 = atomicAdd(&g_cursor[d.w], 1);
        g_edge[p0] = make_int2(s.x, __float_as_int(ev.x));
        g_edge[p1] = make_int2(s.y, __float_as_int(ev.y));
        g_edge[p2] = make_int2(s.z, __float_as_int(ev.z));
        g_edge[p3] = make_int2(s.w, __float_as_int(ev.w));
    } else {
        for (int q = 0; q < 4; q++) {
            int i = base + q;
            if (i < nE) {
                int pos = atomicAdd(&g_cursor[dst[i]], 1);
                g_edge[pos] = make_int2(src[i], __float_as_int(e[i]));
            }
        }
    }
}

// ---------------------------------------------------------------------------
// One warp per node; lane owns 4 features. Gathers fp16 rows (uint2 = 4 half),
// converts to fp32, accumulates in fp32. Unroll-4 for MLP.
// ---------------------------------------------------------------------------
__global__ __launch_bounds__(256) void agg_kernel(int nNodes) {
    int warp = (blockIdx.x * blockDim.x + threadIdx.x) >> 5;
    int lane = threadIdx.x & 31;
    if (warp >= nNodes) return;

    const uint2* __restrict__ hrow = (const uint2*)g_h16;   // 32 uint2 per row
    int beg = g_offsets[warp];
    int end = g_offsets[warp + 1];
    int deg = end - beg;

    float4 ap = make_float4(0.f, 0.f, 0.f, 0.f), au = ap;
    float4 ap2 = ap, au2 = ap;

    int j = beg;
    for (; j + 4 <= end; j += 4) {
        int2 p0 = g_edge[j + 0];
        int2 p1 = g_edge[j + 1];
        int2 p2 = g_edge[j + 2];
        int2 p3 = g_edge[j + 3];
        uint2 r0 = hrow[p0.x * 32 + lane];
        uint2 r1 = hrow[p1.x * 32 + lane];
        uint2 r2 = hrow[p2.x * 32 + lane];
        uint2 r3 = hrow[p3.x * 32 + lane];
        float e0 = __int_as_float(p0.y), e1 = __int_as_float(p1.y);
        float e2 = __int_as_float(p2.y), e3 = __int_as_float(p3.y);

        float2 a0 = __half22float2(u32_to_h2(r0.x));
        float2 b0 = __half22float2(u32_to_h2(r0.y));
        ap.x += a0.x * e0; ap.y += a0.y * e0; ap.z += b0.x * e0; ap.w += b0.y * e0;
        au.x += a0.x;      au.y += a0.y;      au.z += b0.x;      au.w += b0.y;

        float2 a1 = __half22float2(u32_to_h2(r1.x));
        float2 b1 = __half22float2(u32_to_h2(r1.y));
        ap2.x += a1.x * e1; ap2.y += a1.y * e1; ap2.z += b1.x * e1; ap2.w += b1.y * e1;
        au2.x += a1.x;      au2.y += a1.y;      au2.z += b1.x;      au2.w += b1.y;

        float2 a2 = __half22float2(u32_to_h2(r2.x));
        float2 b2 = __half22float2(u32_to_h2(r2.y));
        ap.x += a2.x * e2; ap.y += a2.y * e2; ap.z += b2.x * e2; ap.w += b2.y * e2;
        au.x += a2.x;      au.y += a2.y;      au.z += b2.x;      au.w += b2.y;

        float2 a3 = __half22float2(u32_to_h2(r3.x));
        float2 b3 = __half22float2(u32_to_h2(r3.y));
        ap2.x += a3.x * e3; ap2.y += a3.y * e3; ap2.z += b3.x * e3; ap2.w += b3.y * e3;
        au2.x += a3.x;      au2.y += a3.y;      au2.z += b3.x;      au2.w += b3.y;
    }
    for (; j < end; j++) {
        int2 p = g_edge[j];
        uint2 r = hrow[p.x * 32 + lane];
        float ev = __int_as_float(p.y);
        float2 a = __half22float2(u32_to_h2(r.x));
        float2 b = __half22float2(u32_to_h2(r.y));
        ap.x += a.x * ev; ap.y += a.y * ev; ap.z += b.x * ev; ap.w += b.y * ev;
        au.x += a.x;      au.y += a.y;      au.z += b.x;      au.w += b.y;
    }
    ap.x += ap2.x; ap.y += ap2.y; ap.z += ap2.z; ap.w += ap2.w;
    au.x += au2.x; au.y += au2.y; au.z += au2.z; au.w += au2.w;

    float inv = 1.f / (float)max(deg, 1);
    ((float4*)g_hp)[warp * 32 + lane] =
        make_float4(ap.x * inv, ap.y * inv, ap.z * inv, ap.w * inv);
    ((float4*)g_hu)[warp * 32 + lane] =
        make_float4(au.x * inv, au.y * inv, au.z * inv, au.w * inv);
}

// ---------------------------------------------------------------------------
// FFMA2 GEMM core: BM=64, BN=128, BK=16, 256 threads, 4x8 micro-tile with
// row pairs packed for fma.rn.f32x2. B stored duplicated {w,w} in smem.
// ---------------------------------------------------------------------------
#define BM 64
#define BN 128
#define BK 16
#define XS_LD 68

struct GemmSmem {
    float Xs[BK][XS_LD];
    float Wdup[BK][2 * BN];
};

__device__ __forceinline__ void gemm_tile(
    GemmSmem& sm, const float* __restrict__ Xp, int kl, int k0abs,
    int m0, int M, int tid, int tx, int ty, unsigned long long acc[2][8])
{
    {
        int row = tid >> 2;
        int cg  = tid & 3;
        int gr  = m0 + row;
        if (gr >= M) gr = M - 1;
        float4 v = *(const float4*)&Xp[gr * F + kl + cg * 4];
        sm.Xs[cg * 4 + 0][row] = v.x;
        sm.Xs[cg * 4 + 1][row] = v.y;
        sm.Xs[cg * 4 + 2][row] = v.z;
        sm.Xs[cg * 4 + 3][row] = v.w;
    }
    {
        int n  = tid >> 1;
        int c8 = (tid & 1) * 8;
        float4 v0 = *(const float4*)&g_W[n * (3 * F) + k0abs + c8];
        float4 v1 = *(const float4*)&g_W[n * (3 * F) + k0abs + c8 + 4];
        float wv[8] = {v0.x, v0.y, v0.z, v0.w, v1.x, v1.y, v1.z, v1.w};
        #pragma unroll
        for (int q = 0; q < 8; q++)
            *(float2*)&sm.Wdup[c8 + q][2 * n] = make_float2(wv[q], wv[q]);
    }
    __syncthreads();

    #pragma unroll
    for (int k = 0; k < BK; k++) {
        ulonglong2 a2 = *(const ulonglong2*)&sm.Xs[k][ty * 4];
        unsigned long long ap0 = a2.x, ap1 = a2.y;
        #pragma unroll
        for (int m = 0; m < 8; m++) {
            unsigned long long b2 =
                *(const unsigned long long*)&sm.Wdup[k][2 * (tx + 16 * m)];
            asm("fma.rn.f32x2 %0, %1, %2, %0;" : "+l"(acc[0][m])
                : "l"(ap0), "l"(b2));
            asm("fma.rn.f32x2 %0, %1, %2, %0;" : "+l"(acc[1][m])
                : "l"(ap1), "l"(b2));
        }
    }
    __syncthreads();
}

// out = h @ A^T + bias   (seg 0 of g_W)
__global__ __launch_bounds__(256) void gemm_h_kernel(
    const float* __restrict__ h, float* __restrict__ out, int M)
{
    __shared__ GemmSmem sm;
    int tid = threadIdx.x, tx = tid & 15, ty = tid >> 4;
    int m0 = blockIdx.x * BM;

    unsigned long long acc[2][8];
    #pragma unroll
    for (int p = 0; p < 2; p++)
        #pragma unroll
        for (int m = 0; m < 8; m++) acc[p][m] = 0ull;

    for (int kt = 0; kt < 8; kt++)
        gemm_tile(sm, h, kt * BK, kt * BK, m0, M, tid, tx, ty, acc);

    #pragma unroll
    for (int p = 0; p < 2; p++) {
        int r0 = m0 + ty * 4 + p * 2;
        #pragma unroll
        for (int m = 0; m < 8; m++) {
            int col = tx + 16 * m;
            float bv = g_bias[col];
            unsigned lo = (unsigned)(acc[p][m] & 0xffffffffull);
            unsigned hi = (unsigned)(acc[p][m] >> 32);
            if (r0 < M)     out[r0 * F + col]       = __uint_as_float(lo) + bv;
            if (r0 + 1 < M) out[(r0 + 1) * F + col] = __uint_as_float(hi) + bv;
        }
    }
}

// out += hp @ B^T + hu @ C^T   (segs 1,2 of g_W)
__global__ __launch_bounds__(256) void gemm_pu_kernel(
    float* __restrict__ out, int M)
{
    __shared__ GemmSmem sm;
    int tid = threadIdx.x, tx = tid & 15, ty = tid >> 4;
    int m0 = blockIdx.x * BM;

    unsigned long long acc[2][8];
    #pragma unroll
    for (int p = 0; p < 2; p++)
        #pragma unroll
        for (int m = 0; m < 8; m++) acc[p][m] = 0ull;

    for (int kt = 0; kt < 16; kt++) {
        const float* Xp = (kt < 8) ? g_hp : g_hu;
        int kl = (kt & 7) * BK;
        gemm_tile(sm, Xp, kl, F + kt * BK, m0, M, tid, tx, ty, acc);
    }

    #pragma unroll
    for (int p = 0; p < 2; p++) {
        int r0 = m0 + ty * 4 + p * 2;
        #pragma unroll
        for (int m = 0; m < 8; m++) {
            int col = tx + 16 * m;
            unsigned lo = (unsigned)(acc[p][m] & 0xffffffffull);
            unsigned hi = (unsigned)(acc[p][m] >> 32);
            if (r0 < M)
                out[r0 * F + col] += __uint_as_float(lo);
            if (r0 + 1 < M)
                out[(r0 + 1) * F + col] += __uint_as_float(hi);
        }
    }
}

// ---------------------------------------------------------------------------
extern "C" void kernel_launch(void* const* d_in, const int* in_sizes, int n_in,
                              void* d_out, int out_size) {
    const float* h     = (const float*)d_in[0];
    const float* e     = (const float*)d_in[1];
    const int*   src   = (const int*)d_in[2];
    const int*   dst   = (const int*)d_in[3];
    const float* Ws_w  = (const float*)d_in[4];
    const float* Ws_b  = (const float*)d_in[5];
    const float* Wn_w  = (const float*)d_in[6];
    const float* Wn_b  = (const float*)d_in[7];
    const float* Wu_w  = (const float*)d_in[8];
    const float* Wu_b  = (const float*)d_in[9];
    const float* lin_w = (const float*)d_in[10];
    const float* lin_b = (const float*)d_in[11];
    float* out = (float*)d_out;

    int M = in_sizes[0] / F;
    int E = in_sizes[2];
    if (M > SCAN_N) M = SCAN_N;
    if (E > EDGES_CAP) E = EDGES_CAP;

    // Fork a side stream for {convert_h16, gemm_h}. Handles are created fresh
    // each call and intentionally never destroyed (kernel_launch is invoked
    // only a handful of times; avoids destroy-during-capture hazards).
    cudaStream_t s2;
    cudaStreamCreateWithFlags(&s2, cudaStreamNonBlocking);
    cudaEvent_t evStart, evA, evB, evC;
    cudaEventCreateWithFlags(&evStart, cudaEventDisableTiming);
    cudaEventCreateWithFlags(&evA, cudaEventDisableTiming);
    cudaEventCreateWithFlags(&evB, cudaEventDisableTiming);
    cudaEventCreateWithFlags(&evC, cudaEventDisableTiming);

    cudaEventRecord(evStart, 0);
    cudaStreamWaitEvent(s2, evStart, 0);

    // s2: fp16 conversion of h (independent of everything on legacy)
    int nElem8 = (M * F) / 8;
    convert_h16_kernel<<<(nElem8 + 255) / 256, 256, 0, s2>>>(h, nElem8);
    cudaEventRecord(evC, s2);

    // legacy: fused weights + histogram
    int histBlocks = (E + 1023) / 1024;
    fuse_hist_kernel<<<F + histBlocks, 256>>>(lin_w, lin_b, Ws_w, Wn_w, Wu_w,
                                              Ws_b, Wn_b, Wu_b, dst, E);
    cudaEventRecord(evA, 0);

    // s2: h @ A^T + bias (needs fused weights only)
    cudaStreamWaitEvent(s2, evA, 0);
    gemm_h_kernel<<<(M + BM - 1) / BM, 256, 0, s2>>>(h, out, M);
    cudaEventRecord(evB, s2);

    // legacy: scan -> scatter -> agg (agg also needs convert_h16)
    scan_kernel<<<1, 1024>>>();
    scatter_kernel<<<(E + 1023) / 1024, 256>>>(src, dst, e, E);
    cudaStreamWaitEvent(0, evC, 0);
    agg_kernel<<<(M + 7) / 8, 256>>>(M);

    // join: accumulate aggregated parts into out
    cudaStreamWaitEvent(0, evB, 0);
    gemm_pu_kernel<<<(M + BM - 1) / BM, 256>>>(out, M);
}

// round 8
// speedup vs baseline: 1.2184x; 1.0135x over previous
#include <cuda_runtime.h>
#include <cuda_fp16.h>
#include <cstring>

// ---------------------------------------------------------------------------
// GNN layer:
//   out = h@A^T + mean_dst(h[src]*e)@B^T + mean_dst(h[src])@C^T + b_total
// A = lin@Ws, B = lin@Wn, C = lin@Wu folded on-device.
//
// Graph (5 kernels, 2 events):
//   legacy: mega(fuse ∥ convert_h16 ∥ hist + embedded scan) -> scatter
//           -> agg -> gemm_pu
//   s2:     gemm_h (h@A^T + bias), forked after mega, joins before gemm_pu.
// Scan is executed by the last-finishing hist block (ticket counter) and
// writes only g_cursor; after scatter, cursor[i] == row_end(i), so agg uses
// beg = cursor[i-1], end = cursor[i].
// ---------------------------------------------------------------------------

#define F 128
#define EDGES_CAP 640000
#define SCAN_N 12288            // 256 threads * 48 elems, >= n_nodes

static __device__ int     g_counts[SCAN_N + 4];    // zero-init; scan re-zeroes
static __device__ int     g_cursor[SCAN_N + 4];    // excl. prefix -> row ends
static __device__ int     g_done;                  // hist-block ticket
static __device__ int2    g_edge[EDGES_CAP];       // {src, bits(e)} sorted by dst
static __device__ __half  g_h16[SCAN_N * F];       // fp16 copy of h
static __device__ float   g_hp[SCAN_N * F];        // mean(h[src]*e)
static __device__ float   g_hu[SCAN_N * F];        // mean(h[src])
static __device__ float   g_W[F * 3 * F];          // [128][384] row-major [A|B|C]
static __device__ float   g_bias[F];

// bit-cast helpers (compile to MOV)
__device__ __forceinline__ unsigned h2_to_u32(__half2 v) {
    unsigned u; memcpy(&u, &v, 4); return u;
}
__device__ __forceinline__ __half2 u32_to_h2(unsigned u) {
    __half2 v; memcpy(&v, &u, 4); return v;
}

// ---------------------------------------------------------------------------
// Embedded single-block exclusive scan over SCAN_N counts -> g_cursor.
// 256 threads, 48 elems each. Also zeroes g_counts for the next replay.
// ---------------------------------------------------------------------------
__device__ void scan_embedded(int tid) {
    __shared__ int wsum[8];
    int lane = tid & 31, wid = tid >> 5;

    int4* c4 = (int4*)g_counts;
    int4* k4 = (int4*)g_cursor;

    int v[48];
    int local = 0;
    #pragma unroll
    for (int q = 0; q < 12; q++) {
        int4 a = c4[tid * 12 + q];
        v[q * 4 + 0] = a.x; v[q * 4 + 1] = a.y;
        v[q * 4 + 2] = a.z; v[q * 4 + 3] = a.w;
        local += a.x + a.y + a.z + a.w;
    }

    int inc = local;
    #pragma unroll
    for (int d = 1; d < 32; d <<= 1) {
        int t = __shfl_up_sync(0xffffffffu, inc, d);
        if (lane >= d) inc += t;
    }
    if (lane == 31) wsum[wid] = inc;
    __syncthreads();
    if (tid == 0) {
        int run = 0;
        #pragma unroll
        for (int w = 0; w < 8; w++) { int t = wsum[w]; wsum[w] = run; run += t; }
    }
    __syncthreads();

    int run = wsum[wid] + (inc - local);
    int4 z = make_int4(0, 0, 0, 0);
    #pragma unroll
    for (int q = 0; q < 12; q++) {
        int4 o;
        o.x = run; run += v[q * 4 + 0];
        o.y = run; run += v[q * 4 + 1];
        o.z = run; run += v[q * 4 + 2];
        o.w = run; run += v[q * 4 + 3];
        k4[tid * 12 + q] = o;
        c4[tid * 12 + q] = z;              // self-zero for next replay
    }
}

// ---------------------------------------------------------------------------
// Mega kernel. Block ranges:
//   [0, F)                 : fuse weights (row n = blockIdx.x)
//   [F, F+convBlocks)      : fp32 -> fp16 conversion of h
//   [F+convBlocks, ...)    : histogram of dst (8 edges/thread); the last
//                            hist block to finish runs the embedded scan.
// ---------------------------------------------------------------------------
__global__ __launch_bounds__(256) void mega_kernel(
    const float* __restrict__ lin_w, const float* __restrict__ lin_b,
    const float* __restrict__ Ws_w, const float* __restrict__ Wn_w,
    const float* __restrict__ Wu_w,
    const float* __restrict__ Ws_b, const float* __restrict__ Wn_b,
    const float* __restrict__ Wu_b,
    const float* __restrict__ h, int nElem8, int convBlocks,
    const int* __restrict__ dst, int nE, int histBlocks)
{
    int tid = threadIdx.x;
    int b = blockIdx.x;

    if (b < F) {
        // ---- fuse weights: row b of A|B|C and bias ----
        int n = b;
        __shared__ float linrow[F];
        if (tid < F) linrow[tid] = lin_w[n * F + tid];
        __syncthreads();

        for (int cc = tid; cc < 3 * F; cc += 256) {
            int seg = cc >> 7, i = cc & 127;
            const float* Wp = (seg == 0) ? Ws_w : (seg == 1) ? Wn_w : Wu_w;
            float s = 0.f;
            #pragma unroll 8
            for (int j = 0; j < F; j++)
                s += linrow[j] * Wp[j * F + i];
            g_W[n * (3 * F) + cc] = s;
        }
        if (tid < 32) {
            float s = 0.f;
            #pragma unroll
            for (int m = 0; m < 4; m++) {
                int j = tid + m * 32;
                s += linrow[j] * (Ws_b[j] + Wn_b[j] + Wu_b[j]);
            }
            #pragma unroll
            for (int d = 16; d > 0; d >>= 1)
                s += __shfl_xor_sync(0xffffffffu, s, d);
            if (tid == 0) g_bias[n] = s + lin_b[n];
        }
    } else if (b < F + convBlocks) {
        // ---- fp16 conversion ----
        int i = (b - F) * 256 + tid;
        if (i < nElem8) {
            float4 a = *(const float4*)&h[i * 8];
            float4 c = *(const float4*)&h[i * 8 + 4];
            uint4 o;
            o.x = h2_to_u32(__floats2half2_rn(a.x, a.y));
            o.y = h2_to_u32(__floats2half2_rn(a.z, a.w));
            o.z = h2_to_u32(__floats2half2_rn(c.x, c.y));
            o.w = h2_to_u32(__floats2half2_rn(c.z, c.w));
            *(uint4*)&g_h16[i * 8] = o;
        }
    } else {
        // ---- histogram, 8 edges/thread ----
        int hb = b - F - convBlocks;
        int base = (hb * 256 + tid) * 8;
        if (base + 7 < nE) {
            int4 d0 = *(const int4*)&dst[base];
            int4 d1 = *(const int4*)&dst[base + 4];
            atomicAdd(&g_counts[d0.x], 1); atomicAdd(&g_counts[d0.y], 1);
            atomicAdd(&g_counts[d0.z], 1); atomicAdd(&g_counts[d0.w], 1);
            atomicAdd(&g_counts[d1.x], 1); atomicAdd(&g_counts[d1.y], 1);
            atomicAdd(&g_counts[d1.z], 1); atomicAdd(&g_counts[d1.w], 1);
        } else {
            for (int q = 0; q < 8; q++)
                if (base + q < nE) atomicAdd(&g_counts[dst[base + q]], 1);
        }

        // last hist block to finish runs the scan
        __threadfence();
        __syncthreads();
        __shared__ int ticket;
        if (tid == 0) ticket = atomicAdd(&g_done, 1);
        __syncthreads();
        if (ticket == histBlocks - 1) {
            if (tid == 0) atomicExch(&g_done, 0);   // reset for next replay
            __threadfence();
            scan_embedded(tid);
        }
    }
}

// ---------------------------------------------------------------------------
__global__ __launch_bounds__(256) void scatter_kernel(
    const int* __restrict__ src, const int* __restrict__ dst,
    const float* __restrict__ e, int nE)
{
    int base = (blockIdx.x * blockDim.x + threadIdx.x) * 8;
    if (base + 7 < nE) {
        int4   s0 = *(const int4*)&src[base];
        int4   s1 = *(const int4*)&src[base + 4];
        int4   d0 = *(const int4*)&dst[base];
        int4   d1 = *(const int4*)&dst[base + 4];
        float4 e0 = *(const float4*)&e[base];
        float4 e1 = *(const float4*)&e[base + 4];
        int p0 = atomicAdd(&g_cursor[d0.x], 1);
        int p1 = atomicAdd(&g_cursor[d0.y], 1);
        int p2 = atomicAdd(&g_cursor[d0.z], 1);
        int p3 = atomicAdd(&g_cursor[d0.w], 1);
        g_edge[p0] = make_int2(s0.x, __float_as_int(e0.x));
        g_edge[p1] = make_int2(s0.y, __float_as_int(e0.y));
        g_edge[p2] = make_int2(s0.z, __float_as_int(e0.z));
        g_edge[p3] = make_int2(s0.w, __float_as_int(e0.w));
        int p4 = atomicAdd(&g_cursor[d1.x], 1);
        int p5 = atomicAdd(&g_cursor[d1.y], 1);
        int p6 = atomicAdd(&g_cursor[d1.z], 1);
        int p7 = atomicAdd(&g_cursor[d1.w], 1);
        g_edge[p4] = make_int2(s1.x, __float_as_int(e1.x));
        g_edge[p5] = make_int2(s1.y, __float_as_int(e1.y));
        g_edge[p6] = make_int2(s1.z, __float_as_int(e1.z));
        g_edge[p7] = make_int2(s1.w, __float_as_int(e1.w));
    } else {
        for (int q = 0; q < 8; q++) {
            int i = base + q;
            if (i < nE) {
                int pos = atomicAdd(&g_cursor[dst[i]], 1);
                g_edge[pos] = make_int2(src[i], __float_as_int(e[i]));
            }
        }
    }
}

// ---------------------------------------------------------------------------
// One warp per node. After scatter, g_cursor[i] == end(i); beg = cursor[i-1].
// Gathers fp16 rows (uint2 = 4 half), fp32 accumulate, unroll-4.
// ---------------------------------------------------------------------------
__global__ __launch_bounds__(256) void agg_kernel(int nNodes) {
    int warp = (blockIdx.x * blockDim.x + threadIdx.x) >> 5;
    int lane = threadIdx.x & 31;
    if (warp >= nNodes) return;

    const uint2* __restrict__ hrow = (const uint2*)g_h16;   // 32 uint2 per row
    int beg = (warp == 0) ? 0 : g_cursor[warp - 1];
    int end = g_cursor[warp];
    int deg = end - beg;

    float4 ap = make_float4(0.f, 0.f, 0.f, 0.f), au = ap;
    float4 ap2 = ap, au2 = ap;

    int j = beg;
    for (; j + 4 <= end; j += 4) {
        int2 p0 = g_edge[j + 0];
        int2 p1 = g_edge[j + 1];
        int2 p2 = g_edge[j + 2];
        int2 p3 = g_edge[j + 3];
        uint2 r0 = hrow[p0.x * 32 + lane];
        uint2 r1 = hrow[p1.x * 32 + lane];
        uint2 r2 = hrow[p2.x * 32 + lane];
        uint2 r3 = hrow[p3.x * 32 + lane];
        float e0 = __int_as_float(p0.y), e1 = __int_as_float(p1.y);
        float e2 = __int_as_float(p2.y), e3 = __int_as_float(p3.y);

        float2 a0 = __half22float2(u32_to_h2(r0.x));
        float2 b0 = __half22float2(u32_to_h2(r0.y));
        ap.x += a0.x * e0; ap.y += a0.y * e0; ap.z += b0.x * e0; ap.w += b0.y * e0;
        au.x += a0.x;      au.y += a0.y;      au.z += b0.x;      au.w += b0.y;

        float2 a1 = __half22float2(u32_to_h2(r1.x));
        float2 b1 = __half22float2(u32_to_h2(r1.y));
        ap2.x += a1.x * e1; ap2.y += a1.y * e1; ap2.z += b1.x * e1; ap2.w += b1.y * e1;
        au2.x += a1.x;      au2.y += a1.y;      au2.z += b1.x;      au2.w += b1.y;

        float2 a2 = __half22float2(u32_to_h2(r2.x));
        float2 b2 = __half22float2(u32_to_h2(r2.y));
        ap.x += a2.x * e2; ap.y += a2.y * e2; ap.z += b2.x * e2; ap.w += b2.y * e2;
        au.x += a2.x;      au.y += a2.y;      au.z += b2.x;      au.w += b2.y;

        float2 a3 = __half22float2(u32_to_h2(r3.x));
        float2 b3 = __half22float2(u32_to_h2(r3.y));
        ap2.x += a3.x * e3; ap2.y += a3.y * e3; ap2.z += b3.x * e3; ap2.w += b3.y * e3;
        au2.x += a3.x;      au2.y += a3.y;      au2.z += b3.x;      au2.w += b3.y;
    }
    for (; j < end; j++) {
        int2 p = g_edge[j];
        uint2 r = hrow[p.x * 32 + lane];
        float ev = __int_as_float(p.y);
        float2 a = __half22float2(u32_to_h2(r.x));
        float2 b = __half22float2(u32_to_h2(r.y));
        ap.x += a.x * ev; ap.y += a.y * ev; ap.z += b.x * ev; ap.w += b.y * ev;
        au.x += a.x;      au.y += a.y;      au.z += b.x;      au.w += b.y;
    }
    ap.x += ap2.x; ap.y += ap2.y; ap.z += ap2.z; ap.w += ap2.w;
    au.x += au2.x; au.y += au2.y; au.z += au2.z; au.w += au2.w;

    float inv = 1.f / (float)max(deg, 1);
    ((float4*)g_hp)[warp * 32 + lane] =
        make_float4(ap.x * inv, ap.y * inv, ap.z * inv, ap.w * inv);
    ((float4*)g_hu)[warp * 32 + lane] =
        make_float4(au.x * inv, au.y * inv, au.z * inv, au.w * inv);
}

// ---------------------------------------------------------------------------
// FFMA2 GEMM core: BM=64, BN=128, BK=16, 256 threads, 4x8 micro-tile with
// row pairs packed for fma.rn.f32x2. B stored duplicated {w,w} in smem.
// ---------------------------------------------------------------------------
#define BM 64
#define BN 128
#define BK 16
#define XS_LD 68

struct GemmSmem {
    float Xs[BK][XS_LD];
    float Wdup[BK][2 * BN];
};

__device__ __forceinline__ void gemm_tile(
    GemmSmem& sm, const float* __restrict__ Xp, int kl, int k0abs,
    int m0, int M, int tid, int tx, int ty, unsigned long long acc[2][8])
{
    {
        int row = tid >> 2;
        int cg  = tid & 3;
        int gr  = m0 + row;
        if (gr >= M) gr = M - 1;
        float4 v = *(const float4*)&Xp[gr * F + kl + cg * 4];
        sm.Xs[cg * 4 + 0][row] = v.x;
        sm.Xs[cg * 4 + 1][row] = v.y;
        sm.Xs[cg * 4 + 2][row] = v.z;
        sm.Xs[cg * 4 + 3][row] = v.w;
    }
    {
        int n  = tid >> 1;
        int c8 = (tid & 1) * 8;
        float4 v0 = *(const float4*)&g_W[n * (3 * F) + k0abs + c8];
        float4 v1 = *(const float4*)&g_W[n * (3 * F) + k0abs + c8 + 4];
        float wv[8] = {v0.x, v0.y, v0.z, v0.w, v1.x, v1.y, v1.z, v1.w};
        #pragma unroll
        for (int q = 0; q < 8; q++)
            *(float2*)&sm.Wdup[c8 + q][2 * n] = make_float2(wv[q], wv[q]);
    }
    __syncthreads();

    #pragma unroll
    for (int k = 0; k < BK; k++) {
        ulonglong2 a2 = *(const ulonglong2*)&sm.Xs[k][ty * 4];
        unsigned long long ap0 = a2.x, ap1 = a2.y;
        #pragma unroll
        for (int m = 0; m < 8; m++) {
            unsigned long long b2 =
                *(const unsigned long long*)&sm.Wdup[k][2 * (tx + 16 * m)];
            asm("fma.rn.f32x2 %0, %1, %2, %0;" : "+l"(acc[0][m])
                : "l"(ap0), "l"(b2));
            asm("fma.rn.f32x2 %0, %1, %2, %0;" : "+l"(acc[1][m])
                : "l"(ap1), "l"(b2));
        }
    }
    __syncthreads();
}

// out = h @ A^T + bias   (seg 0 of g_W)
__global__ __launch_bounds__(256) void gemm_h_kernel(
    const float* __restrict__ h, float* __restrict__ out, int M)
{
    __shared__ GemmSmem sm;
    int tid = threadIdx.x, tx = tid & 15, ty = tid >> 4;
    int m0 = blockIdx.x * BM;

    unsigned long long acc[2][8];
    #pragma unroll
    for (int p = 0; p < 2; p++)
        #pragma unroll
        for (int m = 0; m < 8; m++) acc[p][m] = 0ull;

    for (int kt = 0; kt < 8; kt++)
        gemm_tile(sm, h, kt * BK, kt * BK, m0, M, tid, tx, ty, acc);

    #pragma unroll
    for (int p = 0; p < 2; p++) {
        int r0 = m0 + ty * 4 + p * 2;
        #pragma unroll
        for (int m = 0; m < 8; m++) {
            int col = tx + 16 * m;
            float bv = g_bias[col];
            unsigned lo = (unsigned)(acc[p][m] & 0xffffffffull);
            unsigned hi = (unsigned)(acc[p][m] >> 32);
            if (r0 < M)     out[r0 * F + col]       = __uint_as_float(lo) + bv;
            if (r0 + 1 < M) out[(r0 + 1) * F + col] = __uint_as_float(hi) + bv;
        }
    }
}

// out += hp @ B^T + hu @ C^T   (segs 1,2 of g_W)
__global__ __launch_bounds__(256) void gemm_pu_kernel(
    float* __restrict__ out, int M)
{
    __shared__ GemmSmem sm;
    int tid = threadIdx.x, tx = tid & 15, ty = tid >> 4;
    int m0 = blockIdx.x * BM;

    unsigned long long acc[2][8];
    #pragma unroll
    for (int p = 0; p < 2; p++)
        #pragma unroll
        for (int m = 0; m < 8; m++) acc[p][m] = 0ull;

    for (int kt = 0; kt < 16; kt++) {
        const float* Xp = (kt < 8) ? g_hp : g_hu;
        int kl = (kt & 7) * BK;
        gemm_tile(sm, Xp, kl, F + kt * BK, m0, M, tid, tx, ty, acc);
    }

    #pragma unroll
    for (int p = 0; p < 2; p++) {
        int r0 = m0 + ty * 4 + p * 2;
        #pragma unroll
        for (int m = 0; m < 8; m++) {
            int col = tx + 16 * m;
            unsigned lo = (unsigned)(acc[p][m] & 0xffffffffull);
            unsigned hi = (unsigned)(acc[p][m] >> 32);
            if (r0 < M)
                out[r0 * F + col] += __uint_as_float(lo);
            if (r0 + 1 < M)
                out[(r0 + 1) * F + col] += __uint_as_float(hi);
        }
    }
}

// ---------------------------------------------------------------------------
extern "C" void kernel_launch(void* const* d_in, const int* in_sizes, int n_in,
                              void* d_out, int out_size) {
    const float* h     = (const float*)d_in[0];
    const float* e     = (const float*)d_in[1];
    const int*   src   = (const int*)d_in[2];
    const int*   dst   = (const int*)d_in[3];
    const float* Ws_w  = (const float*)d_in[4];
    const float* Ws_b  = (const float*)d_in[5];
    const float* Wn_w  = (const float*)d_in[6];
    const float* Wn_b  = (const float*)d_in[7];
    const float* Wu_w  = (const float*)d_in[8];
    const float* Wu_b  = (const float*)d_in[9];
    const float* lin_w = (const float*)d_in[10];
    const float* lin_b = (const float*)d_in[11];
    float* out = (float*)d_out;

    int M = in_sizes[0] / F;
    int E = in_sizes[2];
    if (M > SCAN_N) M = SCAN_N;
    if (E > EDGES_CAP) E = EDGES_CAP;

    int nElem8     = (M * F) / 8;
    int convBlocks = (nElem8 + 255) / 256;
    int histBlocks = (E + 2047) / 2048;

    // Side stream + events (created fresh per call; never destroyed —
    // kernel_launch is invoked only a handful of times).
    cudaStream_t s2;
    cudaStreamCreateWithFlags(&s2, cudaStreamNonBlocking);
    cudaEvent_t evA, evB;
    cudaEventCreateWithFlags(&evA, cudaEventDisableTiming);
    cudaEventCreateWithFlags(&evB, cudaEventDisableTiming);

    // legacy: mega (fuse ∥ convert ∥ hist + embedded scan)
    mega_kernel<<<F + convBlocks + histBlocks, 256>>>(
        lin_w, lin_b, Ws_w, Wn_w, Wu_w, Ws_b, Wn_b, Wu_b,
        h, nElem8, convBlocks, dst, E, histBlocks);
    cudaEventRecord(evA, 0);

    // s2: h @ A^T + bias (needs fused weights from mega)
    cudaStreamWaitEvent(s2, evA, 0);
    gemm_h_kernel<<<(M + BM - 1) / BM, 256, 0, s2>>>(h, out, M);
    cudaEventRecord(evB, s2);

    // legacy: scatter -> agg
    scatter_kernel<<<(E + 2047) / 2048, 256>>>(src, dst, e, E);
    agg_kernel<<<(M + 7) / 8, 256>>>(M);

    // join: accumulate aggregated parts into out
    cudaStreamWaitEvent(0, evB, 0);
    gemm_pu_kernel<<<(M + BM - 1) / BM, 256>>>(out, M);
}